// round 11
// baseline (speedup 1.0000x reference)
#include <cuda_runtime.h>
#include <cuda_fp16.h>

// Weighted 4D LUT interpolation with 4x spatial upscale.
// Shapes: L=4, D=17, S=4, B=4, H=256, W=256, BINSIZE=16.
// lut:    [4,17,17,17,17,4,4] f32  (d_in[0])
// weight: [4,4,256,256]       f32  (d_in[2])
// x:      [4,1,256,256]       f32  (d_in[3])
// out:    [4,1,1024,1024]     f32
//
// fp16 LUT relayout g_lut2h[flat][s][l]: one 128B line per simplex vertex,
// s-major / l-minor (half index = s*4 + l).
// Main kernel: barrier-free. 4 lanes per pixel; every lane of a quad
// redundantly computes its pixel's scalar setup (no smem, no __syncthreads,
// no phase imbalance). Lane q then issues ONE LDG.256 per vertex (its
// contiguous 32B quarter of the 128B line; 5 independent loads hoisted),
// accumulates the 5-vertex k-sum in fp16 HFMA2, combines with weight[l]
// in fp32, and stores its own output row with one STG.128.

#define NPIX   (4 * 256 * 256)
#define D4     83521          // 17^4

// [flat][s][l] fp16: 64 halves = 128B per flat value = 8 uint4.
__device__ __align__(256) uint4 g_lut2h[(size_t)D4 * 8];

__device__ __forceinline__ void ldg256(uint4& a, uint4& b, const void* p)
{
    asm("ld.global.nc.v8.b32 {%0,%1,%2,%3,%4,%5,%6,%7}, [%8];"
        : "=r"(a.x), "=r"(a.y), "=r"(a.z), "=r"(a.w),
          "=r"(b.x), "=r"(b.y), "=r"(b.z), "=r"(b.w)
        : "l"(p));
}

__global__ void __launch_bounds__(256) relayout_kernel(const float* __restrict__ lut)
{
    int t = blockIdx.x * 256 + threadIdx.x;   // one dst uint4 per thread
    if (t >= D4 * 8) return;
    int j    = t & 7;          // s-pair index (s = 2j, 2j+1)
    int flat = t >> 3;

    float2 fl[4];
#pragma unroll
    for (int l = 0; l < 4; ++l)
        fl[l] = __ldg((const float2*)(lut + ((size_t)l * D4 + flat) * 16 + 2 * j));

    __half2 hh[4];
    hh[0] = __floats2half2_rn(fl[0].x, fl[1].x);   // s(2j):   l0,l1
    hh[1] = __floats2half2_rn(fl[2].x, fl[3].x);   // s(2j):   l2,l3
    hh[2] = __floats2half2_rn(fl[0].y, fl[1].y);   // s(2j+1): l0,l1
    hh[3] = __floats2half2_rn(fl[2].y, fl[3].y);   // s(2j+1): l2,l3

    g_lut2h[(size_t)flat * 8 + j] = *reinterpret_cast<uint4*>(hh);
}

__global__ void __launch_bounds__(256) w4dlut_kernel(
    const float* __restrict__ weight,
    const float* __restrict__ x,
    float* __restrict__ out)
{
    int t = blockIdx.x * 256 + threadIdx.x;
    int q = t & 3;          // lane within pixel quad; owns output row sy=q
    int g = t >> 2;         // pixel id
    int w = g & 255;
    int h = (g >> 8) & 255;
    int b = g >> 16;

    // ---- weight loads (independent; issue early) ----
    const float* wp = weight + ((size_t)b * 4 * 65536) + h * 256 + w;
    float wg0 = __ldg(wp);
    float wg1 = __ldg(wp + 65536);
    float wg2 = __ldg(wp + 2 * 65536);
    float wg3 = __ldg(wp + 3 * 65536);

    // ---- per-pixel scalar setup (redundant across the 4 quad lanes) ----
    int h1 = (h + 1 < 256) ? h + 1 : 254;   // reflect pad
    int w1 = (w + 1 < 256) ? w + 1 : 254;

    const float* xb = x + b * 65536;
    float pv[4];
    pv[0] = __ldg(xb + h  * 256 + w );
    pv[1] = __ldg(xb + h  * 256 + w1);
    pv[2] = __ldg(xb + h1 * 256 + w );
    pv[3] = __ldg(xb + h1 * 256 + w1);

    float f[4];
    int   base[4];
#pragma unroll
    for (int d = 0; d < 4; ++d) {
        float tt = pv[d] * (1.0f / 16.0f);
        float bf = floorf(tt);
        f[d] = tt - bf;
        int bi = (int)bf;
        bi = min(max(bi, 0), 15);
        base[d] = bi;
    }

    // stable descending rank (matches jnp.argsort(-frac))
    int rank[4];
#pragma unroll
    for (int d = 0; d < 4; ++d) {
        int r = 0;
#pragma unroll
        for (int e = 0; e < 4; ++e)
            r += (f[e] > f[d]) || (f[e] == f[d] && e < d);
        rank[d] = r;
    }

    const int strides[4] = {4913, 289, 17, 1};
    float sf[4];
    int   sd[4];
#pragma unroll
    for (int r = 0; r < 4; ++r) {
        float v = 0.0f; int s = 0;
#pragma unroll
        for (int d = 0; d < 4; ++d)
            if (rank[d] == r) { v = f[d]; s = strides[d]; }
        sf[r] = v; sd[r] = s;
    }

    float wts[5];
    wts[0] = 1.0f - sf[0];
    wts[1] = sf[0] - sf[1];
    wts[2] = sf[1] - sf[2];
    wts[3] = sf[2] - sf[3];
    wts[4] = sf[3];

    int flat = ((base[0] * 17 + base[1]) * 17 + base[2]) * 17 + base[3];

    // ---- gathers: one LDG.256 per vertex, all 5 hoisted/independent ----
    uint4   v0[5], v1[5];
    __half2 cc[5];
#pragma unroll
    for (int k = 0; k < 5; ++k) {
        if (k) flat += sd[k - 1];
        cc[k] = __float2half2_rn(wts[k]);
        const char* p = (const char*)g_lut2h + ((size_t)flat * 128 + q * 32);
        ldg256(v0[k], v1[k], p);
    }

    // ---- fp16 k-sum: 16 halves = 8 half2 accumulators ----
    __half2 acc[8];
#pragma unroll
    for (int i = 0; i < 8; ++i) acc[i] = __half2half2(__ushort_as_half(0));

#pragma unroll
    for (int k = 0; k < 5; ++k) {
        const __half2* ha = reinterpret_cast<const __half2*>(&v0[k]);
        const __half2* hb = reinterpret_cast<const __half2*>(&v1[k]);
        __half2 c = cc[k];
#pragma unroll
        for (int i = 0; i < 4; ++i) {
            acc[i]     = __hfma2(c, ha[i], acc[i]);
            acc[4 + i] = __hfma2(c, hb[i], acc[4 + i]);
        }
    }

    // ---- fp32 epilogue: o[s_local] = dot over l with weight ----
    float o[4];
#pragma unroll
    for (int i = 0; i < 4; ++i) {
        float2 f01 = __half22float2(acc[2 * i]);
        float2 f23 = __half22float2(acc[2 * i + 1]);
        float v = f01.x * wg0;
        v = fmaf(f01.y, wg1, v);
        v = fmaf(f23.x, wg2, v);
        v = fmaf(f23.y, wg3, v);
        o[i] = v;
    }

    // lane q writes out[b, 0, h*4+q, w*4 .. w*4+3]  (one STG.128)
    float4* op = (float4*)(out + (((size_t)b * 1024 + h * 4 + q) * 1024 + w * 4));
    *op = make_float4(o[0], o[1], o[2], o[3]);
}

extern "C" void kernel_launch(void* const* d_in, const int* in_sizes, int n_in,
                              void* d_out, int out_size)
{
    const float* lut    = (const float*)d_in[0];
    const float* weight = (const float*)d_in[2];
    const float* x      = (const float*)d_in[3];
    float* out          = (float*)d_out;

    relayout_kernel<<<(D4 * 8 + 255) / 256, 256>>>(lut);
    w4dlut_kernel<<<(NPIX * 4) / 256, 256>>>(weight, x, out);
}

// round 12
// speedup vs baseline: 1.1102x; 1.1102x over previous
#include <cuda_runtime.h>
#include <cuda_fp16.h>

// Weighted 4D LUT interpolation with 4x spatial upscale.
// Shapes: L=4, D=17, S=4, B=4, H=256, W=256, BINSIZE=16.
// lut:    [4,17,17,17,17,4,4] f32  (d_in[0])
// weight: [4,4,256,256]       f32  (d_in[2])
// x:      [4,1,256,256]       f32  (d_in[3])
// out:    [4,1,1024,1024]     f32
//
// fp16 LUT relayout g_lut2h[flat][s][l]: one 128B line per simplex vertex,
// s-major / l-minor (half index = s*4 + l).
// Main kernel: barrier-free, 4 lanes/pixel, LDG.256 gathers (5/thread).
// Scalar setup uses a 5-exchange compare-exchange network on (frac,stride)
// pairs instead of rank+select (~25 vs ~80 instr). Unstable ties are safe:
// equal fracs give the in-between vertex weight sf[r]-sf[r+1] = 0, so any
// tie order yields an identical result.

#define NPIX (4 * 256 * 256)
#define D4   83521          // 17^4

// [flat][s][l] fp16: 64 halves = 128B per flat value = 8 uint4.
__device__ __align__(256) uint4 g_lut2h[(size_t)D4 * 8];

__device__ __forceinline__ void ldg256(uint4& a, uint4& b, const void* p)
{
    asm("ld.global.nc.v8.b32 {%0,%1,%2,%3,%4,%5,%6,%7}, [%8];"
        : "=r"(a.x), "=r"(a.y), "=r"(a.z), "=r"(a.w),
          "=r"(b.x), "=r"(b.y), "=r"(b.z), "=r"(b.w)
        : "l"(p));
}

__global__ void __launch_bounds__(256) relayout_kernel(const float* __restrict__ lut)
{
    int t = blockIdx.x * 256 + threadIdx.x;   // one dst uint4 per thread
    if (t >= D4 * 8) return;
    int j    = t & 7;          // s-pair index (s = 2j, 2j+1)
    int flat = t >> 3;

    float2 fl[4];
#pragma unroll
    for (int l = 0; l < 4; ++l)
        fl[l] = __ldg((const float2*)(lut + ((size_t)l * D4 + flat) * 16 + 2 * j));

    __half2 hh[4];
    hh[0] = __floats2half2_rn(fl[0].x, fl[1].x);   // s(2j):   l0,l1
    hh[1] = __floats2half2_rn(fl[2].x, fl[3].x);   // s(2j):   l2,l3
    hh[2] = __floats2half2_rn(fl[0].y, fl[1].y);   // s(2j+1): l0,l1
    hh[3] = __floats2half2_rn(fl[2].y, fl[3].y);   // s(2j+1): l2,l3

    g_lut2h[(size_t)flat * 8 + j] = *reinterpret_cast<uint4*>(hh);
}

__global__ void __launch_bounds__(256) w4dlut_kernel(
    const float* __restrict__ weight,
    const float* __restrict__ x,
    float* __restrict__ out)
{
    int t = blockIdx.x * 256 + threadIdx.x;
    int q = t & 3;          // lane within pixel quad; owns output row sy=q
    int g = t >> 2;         // pixel id
    int w = g & 255;
    int h = (g >> 8) & 255;
    int b = g >> 16;

    // ---- weight loads (independent; issue early) ----
    const float* wp = weight + ((size_t)b * 4 * 65536) + h * 256 + w;
    float wg0 = __ldg(wp);
    float wg1 = __ldg(wp + 65536);
    float wg2 = __ldg(wp + 2 * 65536);
    float wg3 = __ldg(wp + 3 * 65536);

    // ---- per-pixel scalar setup ----
    int h1 = (h + 1 < 256) ? h + 1 : 254;   // reflect pad
    int w1 = (w + 1 < 256) ? w + 1 : 254;

    const float* xb = x + b * 65536;
    float pv[4];
    pv[0] = __ldg(xb + h  * 256 + w );
    pv[1] = __ldg(xb + h  * 256 + w1);
    pv[2] = __ldg(xb + h1 * 256 + w );
    pv[3] = __ldg(xb + h1 * 256 + w1);

    float f[4];
    int   st[4] = {4913, 289, 17, 1};   // per-dim strides, sorted along with f
    int   flat;
    {
        int base[4];
#pragma unroll
        for (int d = 0; d < 4; ++d) {
            float tt = pv[d] * (1.0f / 16.0f);
            float bf = floorf(tt);
            f[d] = tt - bf;
            int bi = (int)bf;
            bi = min(max(bi, 0), 15);
            base[d] = bi;
        }
        flat = ((base[0] * 17 + base[1]) * 17 + base[2]) * 17 + base[3];
    }

    // descending sort of (f, st) pairs: 5-exchange network.
    // Ties are value-safe: equal fracs give the middle vertex zero weight.
#define CSWAP(i, j)                                   \
    {                                                 \
        bool sw = f[i] < f[j];                        \
        float ft = sw ? f[j] : f[i];                  \
        f[j] = sw ? f[i] : f[j];                      \
        f[i] = ft;                                    \
        int  it = sw ? st[j] : st[i];                 \
        st[j] = sw ? st[i] : st[j];                   \
        st[i] = it;                                   \
    }
    CSWAP(0, 1) CSWAP(2, 3) CSWAP(0, 2) CSWAP(1, 3) CSWAP(1, 2)
#undef CSWAP

    float wts[5];
    wts[0] = 1.0f - f[0];
    wts[1] = f[0] - f[1];
    wts[2] = f[1] - f[2];
    wts[3] = f[2] - f[3];
    wts[4] = f[3];

    // ---- gathers: one LDG.256 per vertex, all 5 hoisted/independent ----
    const char* lbase = (const char*)g_lut2h + q * 32;
    unsigned    off   = (unsigned)flat * 128u;

    uint4   v0[5], v1[5];
    __half2 cc[5];
#pragma unroll
    for (int k = 0; k < 5; ++k) {
        if (k) off += (unsigned)st[k - 1] * 128u;
        cc[k] = __float2half2_rn(wts[k]);
        ldg256(v0[k], v1[k], lbase + off);
    }

    // ---- fp16 k-sum: 16 halves = 8 half2 accumulators ----
    __half2 acc[8];
#pragma unroll
    for (int i = 0; i < 8; ++i) acc[i] = __half2half2(__ushort_as_half(0));

#pragma unroll
    for (int k = 0; k < 5; ++k) {
        const __half2* ha = reinterpret_cast<const __half2*>(&v0[k]);
        const __half2* hb = reinterpret_cast<const __half2*>(&v1[k]);
        __half2 c = cc[k];
#pragma unroll
        for (int i = 0; i < 4; ++i) {
            acc[i]     = __hfma2(c, ha[i], acc[i]);
            acc[4 + i] = __hfma2(c, hb[i], acc[4 + i]);
        }
    }

    // ---- fp32 epilogue: o[s_local] = dot over l with weight ----
    float o[4];
#pragma unroll
    for (int i = 0; i < 4; ++i) {
        float2 f01 = __half22float2(acc[2 * i]);
        float2 f23 = __half22float2(acc[2 * i + 1]);
        float v = f01.x * wg0;
        v = fmaf(f01.y, wg1, v);
        v = fmaf(f23.x, wg2, v);
        v = fmaf(f23.y, wg3, v);
        o[i] = v;
    }

    // lane q writes out[b, 0, h*4+q, w*4 .. w*4+3]  (one STG.128)
    float4* op = (float4*)(out + (((size_t)b * 1024 + h * 4 + q) * 1024 + w * 4));
    *op = make_float4(o[0], o[1], o[2], o[3]);
}

extern "C" void kernel_launch(void* const* d_in, const int* in_sizes, int n_in,
                              void* d_out, int out_size)
{
    const float* lut    = (const float*)d_in[0];
    const float* weight = (const float*)d_in[2];
    const float* x      = (const float*)d_in[3];
    float* out          = (float*)d_out;

    relayout_kernel<<<(D4 * 8 + 255) / 256, 256>>>(lut);
    w4dlut_kernel<<<(NPIX * 4) / 256, 256>>>(weight, x, out);
}